// round 15
// baseline (speedup 1.0000x reference)
#include <cuda_runtime.h>
#include <stdint.h>

// ───────────── padded coordinate table: float4 per atom (16B, one sector) ─────────────
#define MAX_ATOMS 100352
__device__ float4 g_R4[MAX_ATOMS];

__global__ void pad_R_kernel(const float* __restrict__ R, int n_atoms) {
    int i = blockIdx.x * blockDim.x + threadIdx.x;
    if (i < n_atoms) {
        g_R4[i] = make_float4(R[3 * i + 0], R[3 * i + 1], R[3 * i + 2], 0.0f);
    }
}

// ───────────── hybrid SMEM-cache + LDG gather kernel ─────────────
#define SMEM_ATOMS 13952                 // 14% of atoms, 223232 B of smem
#define SMEM_BYTES (SMEM_ATOMS * 16)
#define HTPB 1024

__device__ __forceinline__ uint32_t smem_u32(const void* p) {
    uint32_t a;
    asm("{ .reg .u64 t; cvta.to.shared.u64 t, %1; cvt.u32.u64 %0, t; }"
        : "=r"(a) : "l"(p));
    return a;
}

__device__ __forceinline__ int4 ld_stream_int4(const int* p) {
    int4 v;
    asm volatile("ld.global.nc.L1::no_allocate.v4.b32 {%0,%1,%2,%3}, [%4];"
                 : "=r"(v.x), "=r"(v.y), "=r"(v.z), "=r"(v.w) : "l"(p));
    return v;
}
__device__ __forceinline__ void st_stream_float4(float* p, float4 v) {
    asm volatile("st.global.cs.v4.f32 [%0], {%1,%2,%3,%4};"
                 :: "l"(p), "f"(v.x), "f"(v.y), "f"(v.z), "f"(v.w) : "memory");
}

// Fetch atom row: smem if cached, else global. Both sides are volatile asm so
// neither load can be speculated/hoisted; ptxas predicates or branches — only
// lanes on the LDG side generate l1tex gather wavefronts.
__device__ __forceinline__ float4 fetch_atom(int i, uint32_t sbase) {
    float4 v;
    if (i < SMEM_ATOMS) {
        asm volatile("ld.shared.v4.f32 {%0,%1,%2,%3}, [%4];"
                     : "=f"(v.x), "=f"(v.y), "=f"(v.z), "=f"(v.w)
                     : "r"(sbase + (uint32_t)i * 16u));
    } else {
        asm volatile("ld.global.nc.v4.f32 {%0,%1,%2,%3}, [%4];"
                     : "=f"(v.x), "=f"(v.y), "=f"(v.z), "=f"(v.w)
                     : "l"(g_R4 + i));
    }
    return v;
}

__device__ __forceinline__ float dist3(float4 a, float4 b) {
    float dx = a.x - b.x, dy = a.y - b.y, dz = a.z - b.z;
    return sqrtf(dx * dx + dy * dy + dz * dz);
}

__global__ void __launch_bounds__(HTPB, 1)
dist_hybrid_kernel(const int* __restrict__ idx_i,
                   const int* __restrict__ idx_j,
                   float* __restrict__ out,
                   int n_edges) {
    extern __shared__ float4 sR[];
    uint32_t sbase = smem_u32(sR);

    // Cooperative preload of the hot table slice (coalesced from L2).
    #pragma unroll 4
    for (int a = threadIdx.x; a < SMEM_ATOMS; a += HTPB) {
        sR[a] = g_R4[a];
    }
    __syncthreads();

    unsigned tid = blockIdx.x * HTPB + threadIdx.x;
    unsigned nthreads = gridDim.x * HTPB;
    unsigned n = (unsigned)n_edges;
    unsigned nquads = n / 4u;

    // Grid-stride over quads of 4 edges: 2 int4 index loads, 8 gathers
    // (predicated LDS/LDG mix), 1 float4 store.
    for (unsigned q = tid; q < nquads; q += nthreads) {
        unsigned base = q * 4u;
        int4 vi = ld_stream_int4(idx_i + base);
        int4 vj = ld_stream_int4(idx_j + base);

        float4 a0 = fetch_atom(vi.x, sbase);
        float4 b0 = fetch_atom(vj.x, sbase);
        float4 a1 = fetch_atom(vi.y, sbase);
        float4 b1 = fetch_atom(vj.y, sbase);
        float4 a2 = fetch_atom(vi.z, sbase);
        float4 b2 = fetch_atom(vj.z, sbase);
        float4 a3 = fetch_atom(vi.w, sbase);
        float4 b3 = fetch_atom(vj.w, sbase);

        float4 r;
        r.x = dist3(a0, b0);
        r.y = dist3(a1, b1);
        r.z = dist3(a2, b2);
        r.w = dist3(a3, b3);
        st_stream_float4(out + base, r);
    }

    // Scalar tail (n not divisible by 4).
    for (unsigned e = nquads * 4u + tid; e < n; e += nthreads) {
        float4 a = fetch_atom(idx_i[e], sbase);
        float4 b = fetch_atom(idx_j[e], sbase);
        out[e] = dist3(a, b);
    }
}

// ───────────── host ─────────────
extern "C" void kernel_launch(void* const* d_in, const int* in_sizes, int n_in,
                              void* d_out, int out_size) {
    const float* R   = (const float*)d_in[0];
    const int* idx_i = (const int*)d_in[1];
    const int* idx_j = (const int*)d_in[2];
    float* out       = (float*)d_out;

    int n_atoms = in_sizes[0] / 3;
    int n_edges = in_sizes[1];

    {
        int threads = 256;
        int blocks = (n_atoms + threads - 1) / threads;
        pad_R_kernel<<<blocks, threads>>>(R, n_atoms);
    }

    static bool configured = false;
    static int nsm = 148;
    if (!configured) {
        cudaFuncSetAttribute(dist_hybrid_kernel,
                             cudaFuncAttributeMaxDynamicSharedMemorySize, SMEM_BYTES);
        int v = 0;
        if (cudaDeviceGetAttribute(&v, cudaDevAttrMultiProcessorCount, 0) == cudaSuccess
            && v > 0) {
            nsm = v;
        }
        configured = true;
    }

    dist_hybrid_kernel<<<nsm, HTPB, SMEM_BYTES>>>(idx_i, idx_j, out, n_edges);
}

// round 17
// speedup vs baseline: 1.5552x; 1.5552x over previous
#include <cuda_runtime.h>
#include <stdint.h>

// Padded coordinate table: one float4 per atom, 16B-aligned -> every gather is
// a single LDG.E.128 touching exactly one 32B L2 sector.
#define MAX_ATOMS 100352
__device__ float4 g_R4[MAX_ATOMS];

__global__ void pad_R_kernel(const float* __restrict__ R, int n_atoms) {
    int i = blockIdx.x * blockDim.x + threadIdx.x;
    if (i < n_atoms) {
        g_R4[i] = make_float4(R[3 * i + 0], R[3 * i + 1], R[3 * i + 2], 0.0f);
    }
}

// Streaming int4 load that does NOT allocate in L1.
__device__ __forceinline__ int4 ld_stream_int4(const int4* p) {
    int4 v;
    asm volatile("ld.global.nc.L1::no_allocate.v4.b32 {%0,%1,%2,%3}, [%4];"
                 : "=r"(v.x), "=r"(v.y), "=r"(v.z), "=r"(v.w)
                 : "l"(p));
    return v;
}

// Gather load: L2-direct, no L1 line allocation -> no fill wavefronts
// competing with demand wavefronts in l1tex.
__device__ __forceinline__ float4 ld_gather_f4(const float4* p) {
    float4 v;
    asm volatile("ld.global.nc.L1::no_allocate.v4.f32 {%0,%1,%2,%3}, [%4];"
                 : "=f"(v.x), "=f"(v.y), "=f"(v.z), "=f"(v.w)
                 : "l"(p));
    return v;
}

// Streaming store, evict-first (no L1 pollution).
__device__ __forceinline__ void st_stream_float4(float4* p, float4 v) {
    asm volatile("st.global.cs.v4.f32 [%0], {%1,%2,%3,%4};"
                 :
                 : "l"(p), "f"(v.x), "f"(v.y), "f"(v.z), "f"(v.w)
                 : "memory");
}

__device__ __forceinline__ float edge_dist(int i, int j) {
    float4 a = ld_gather_f4(g_R4 + i);
    float4 b = ld_gather_f4(g_R4 + j);
    float dx = a.x - b.x;
    float dy = a.y - b.y;
    float dz = a.z - b.z;
    return sqrtf(dx * dx + dy * dy + dz * dz);
}

// 8 edges per thread: two int4 streaming loads per index array,
// 16 independent gathers in flight, two streaming float4 stores.
__global__ void dist_kernel(const int* __restrict__ idx_i,
                            const int* __restrict__ idx_j,
                            float* __restrict__ out,
                            int n_edges) {
    unsigned t = blockIdx.x * blockDim.x + threadIdx.x;
    unsigned base = t * 8u;

    if (base + 8u <= (unsigned)n_edges) {
        const int4* pi = reinterpret_cast<const int4*>(idx_i + base);
        const int4* pj = reinterpret_cast<const int4*>(idx_j + base);
        int4 i0 = ld_stream_int4(pi + 0);
        int4 i1 = ld_stream_int4(pi + 1);
        int4 j0 = ld_stream_int4(pj + 0);
        int4 j1 = ld_stream_int4(pj + 1);

        float4 r0, r1;
        r0.x = edge_dist(i0.x, j0.x);
        r0.y = edge_dist(i0.y, j0.y);
        r0.z = edge_dist(i0.z, j0.z);
        r0.w = edge_dist(i0.w, j0.w);
        r1.x = edge_dist(i1.x, j1.x);
        r1.y = edge_dist(i1.y, j1.y);
        r1.z = edge_dist(i1.z, j1.z);
        r1.w = edge_dist(i1.w, j1.w);

        st_stream_float4(reinterpret_cast<float4*>(out + base) + 0, r0);
        st_stream_float4(reinterpret_cast<float4*>(out + base) + 1, r1);
    } else if (base < (unsigned)n_edges) {
        for (unsigned e = base; e < (unsigned)n_edges; ++e) {
            out[e] = edge_dist(idx_i[e], idx_j[e]);
        }
    }
}

extern "C" void kernel_launch(void* const* d_in, const int* in_sizes, int n_in,
                              void* d_out, int out_size) {
    const float* R   = (const float*)d_in[0];
    const int* idx_i = (const int*)d_in[1];
    const int* idx_j = (const int*)d_in[2];
    float* out       = (float*)d_out;

    int n_atoms = in_sizes[0] / 3;
    int n_edges = in_sizes[1];

    {
        int threads = 256;
        int blocks = (n_atoms + threads - 1) / threads;
        pad_R_kernel<<<blocks, threads>>>(R, n_atoms);
    }
    {
        int threads = 256;
        int edges_per_block = threads * 8;
        int blocks = (n_edges + edges_per_block - 1) / edges_per_block;
        dist_kernel<<<blocks, threads>>>(idx_i, idx_j, out, n_edges);
    }
}